// round 16
// baseline (speedup 1.0000x reference)
#include <cuda_runtime.h>
#include <cuda_fp16.h>
#include <cstdint>

// out[b,t] = cumsum_t( relu(x @ Wh^T + bh) ) + (x @ Wb^T + bb)
//   x [16384,1024] f32, Wh [512,1024] f32, bh[512], Wb[1,1024], bb[1]
//
// fp16 mma.sync m16n8k16. CTA = 32 rows x 512 cols, 256 threads (8 warps,
// warp tile 32x64), 2 CTAs/SM, warp-independent mainloop (no CTA barriers).
// R16: NO x prepass. Each warp loads the raw fp32 A chunk itself (coalesced
// LDG.128, L1-shared across warps), converts to fp16 in registers, STS.64 in
// FRAGMENT ORDER into its private double-buffered smem ring, then LDS
// fragments. Only __syncwarp per chunk. Base GEMV folded into the convert
// step (chunk c owned by warp c&7; deterministic fixed-order reduction).
// B: fp16 fragment-order gmem (tiny Wh prepass), direct LDG.128
// consume-then-reload. One CTA barrier total (epilogue).

#define DDIM   1024
#define TDIM   512
#define BROWS  16384
#define MTILE  32
#define NCH    32
#define NTHREADS 256

__device__ __half g_whs[TDIM * DDIM];   // B: [chunk][jg][lane][8 halfs]

__device__ __forceinline__ void mma_f16(float* c, uint32_t a0, uint32_t a1,
                                        uint32_t a2, uint32_t a3,
                                        uint32_t b0, uint32_t b1) {
    asm volatile(
        "mma.sync.aligned.m16n8k16.row.col.f32.f16.f16.f32 "
        "{%0,%1,%2,%3}, {%4,%5,%6,%7}, {%8,%9}, {%0,%1,%2,%3};"
        : "+f"(c[0]), "+f"(c[1]), "+f"(c[2]), "+f"(c[3])
        : "r"(a0), "r"(a1), "r"(a2), "r"(a3), "r"(b0), "r"(b1));
}
__device__ __forceinline__ uint32_t f2h2(float lo, float hi) {
    __half2 h = __floats2half2_rn(lo, hi);
    return *(uint32_t*)&h;
}

// prepass: Wh -> fp16 B-fragment order (R15's proven Wh branch; 256 blocks)
__global__ void __launch_bounds__(256) prep_wh_kernel(const float* __restrict__ Wh) {
    __shared__ __half sbuf[2048];
    const int b = blockIdx.x;
    const int t = threadIdx.x;
    const int c   = b >> 3;
    const int rg8 = b & 7;
    const int rl = t >> 2;          // 0..63 local row
    const int q  = t & 3;
    const int T  = rg8 * 64 + rl;
    const float* wrow = Wh + (size_t)T * DDIM + c * 32 + q * 8;
    float4 v0 = *(const float4*)(wrow);
    float4 v1 = *(const float4*)(wrow + 4);

    const int jg_l = rl >> 3;
    const int l4 = T & 7;
    #pragma unroll
    for (int e = 0; e < 8; e++) {
        int k5 = q * 8 + e;
        int G = (k5 >> 4) & 1, u = (k5 >> 3) & 1, lk = (k5 & 7) >> 1, w_ = k5 & 1;
        float f = (e < 4) ? ((const float*)&v0)[e] : ((const float*)&v1)[e - 4];
        sbuf[jg_l * 256 + (4 * l4 + lk) * 8 + 4 * G + 2 * u + w_] =
            __float2half_rn(f);
    }
    __syncthreads();
    *(uint4*)((char*)g_whs + (size_t)c * 32768 + rg8 * 4096 + t * 16) =
        *(const uint4*)((const char*)sbuf + t * 16);
}

__global__ void __launch_bounds__(NTHREADS, 2)
surv_f16k_kernel(const float* __restrict__ x,
                 const float* __restrict__ bh,
                 const float* __restrict__ Wb,
                 const float* __restrict__ bb,
                 float* __restrict__ out)
{
    __shared__ __align__(16) char As[8 * 2 * 2048];   // per-warp 2-stage A rings
    __shared__ float seg_s[MTILE * 8];
    __shared__ float bsum_s[MTILE * 8];

    const int tid  = threadIdx.x;
    const int nw   = tid >> 5;
    const int lane = tid & 31;
    const int l4   = lane >> 2;    // == r0
    const int lk   = lane & 3;     // == q0
    const int tile = blockIdx.x;
    const int row0 = tile * MTILE;

    // A convert addressing (per-lane constants)
    const int r0 = l4;             // base row 0..7 (rows r0, r0+8, r0+16, r0+24)
    const int q0 = lk;             // float4 group (q0 and q0+4)
    const char* xbase = (const char*)(x + (size_t)(row0 + r0) * DDIM);
    char* ring = As + nw * 4096;
    // STS byte offsets: for q: G=q>>2, u=(q>>1)&1, lkw=(q&1)*2
    //   p(ii,q) = (ii*2+G)*512 + (4*r0+lkw)*16 + 8*u  ; h23 at +16
    int poff[2][2];
    #pragma unroll
    for (int qi = 0; qi < 2; qi++) {
        int q = q0 + 4 * qi;
        int G = q >> 2, u = (q >> 1) & 1, lkw = (q & 1) * 2;
        #pragma unroll
        for (int ii = 0; ii < 2; ii++)
            poff[qi][ii] = (ii * 2 + G) * 512 + (4 * r0 + lkw) * 16 + 8 * u;
    }

    // B direct-LDG base
    const char* bgm = (const char*)g_whs + nw * 4096 + lane * 16;

    float acc[2][8][4];
    #pragma unroll
    for (int i = 0; i < 2; i++)
        #pragma unroll
        for (int j = 0; j < 8; j++)
            #pragma unroll
            for (int q = 0; q < 4; q++) acc[i][j][q] = 0.f;
    float bacc[4] = {0.f, 0.f, 0.f, 0.f};

    uint4 LB[8];
    #pragma unroll
    for (int j = 0; j < 8; j++)
        LB[j] = *(const uint4*)(bgm + j * 512);

    // ---- mainloop: warp-independent (only __syncwarp) ----
    #pragma unroll 1
    for (int c = 0; c < NCH; c++) {
        char* buf = ring + (c & 1) * 2048;
        const int koff = c * 128 + q0 * 16;   // byte offset into x row
        const bool mine = ((c & 7) == nw);

        // convert fp32 x -> fp16 fragments in warp-private ring (+ base GEMV)
        #pragma unroll
        for (int qi = 0; qi < 2; qi++) {
            const int ko = koff + qi * 64;
            float4 wq;
            if (mine) wq = *(const float4*)((const char*)Wb + c * 128 +
                                            q0 * 16 + qi * 64);
            #pragma unroll
            for (int ii = 0; ii < 2; ii++) {
                float4 fa = *(const float4*)(xbase + (size_t)ii * 65536 + ko);
                float4 fb = *(const float4*)(xbase + (size_t)ii * 65536 + 32768 + ko);
                if (mine) {
                    float pa = fmaf(fa.x, wq.x, fmaf(fa.y, wq.y,
                               fmaf(fa.z, wq.z, fa.w * wq.w)));
                    float pb = fmaf(fb.x, wq.x, fmaf(fb.y, wq.y,
                               fmaf(fb.z, wq.z, fb.w * wq.w)));
                    bacc[2 * ii]     += pa;
                    bacc[2 * ii + 1] += pb;
                }
                uint2 h01 = make_uint2(f2h2(fa.x, fa.y), f2h2(fb.x, fb.y));
                uint2 h23 = make_uint2(f2h2(fa.z, fa.w), f2h2(fb.z, fb.w));
                *(uint2*)(buf + poff[qi][ii])      = h01;
                *(uint2*)(buf + poff[qi][ii] + 16) = h23;
            }
        }
        __syncwarp();

        // LDS fragments (base + lane*16, conflict-free)
        const char* xaddr = buf + lane * 16;
        uint4 LA00 = *(const uint4*)(xaddr);
        uint4 LA01 = *(const uint4*)(xaddr + 512);
        uint4 LA10 = *(const uint4*)(xaddr + 1024);
        uint4 LA11 = *(const uint4*)(xaddr + 1536);

        const char* bnext = bgm + (size_t)((c + 1 < NCH) ? (c + 1) : c) * 32768;
        #pragma unroll
        for (int j = 0; j < 8; j++) {
            uint4 b = LB[j];
            mma_f16(acc[0][j], LA00.x, LA00.y, LA00.z, LA00.w, b.x, b.y);
            mma_f16(acc[1][j], LA10.x, LA10.y, LA10.z, LA10.w, b.x, b.y);
            mma_f16(acc[0][j], LA01.x, LA01.y, LA01.z, LA01.w, b.z, b.w);
            mma_f16(acc[1][j], LA11.x, LA11.y, LA11.z, LA11.w, b.z, b.w);
            LB[j] = *(const uint4*)(bnext + j * 512);
        }
    }

    // ---- base partials: reduce over the 4 q-lanes of each row group ----
    #pragma unroll
    for (int s = 0; s < 4; s++) {
        bacc[s] += __shfl_down_sync(0xffffffffu, bacc[s], 2, 4);
        bacc[s] += __shfl_down_sync(0xffffffffu, bacc[s], 1, 4);
        if (q0 == 0) bsum_s[(r0 + 8 * s) * 8 + nw] = bacc[s];
    }

    // ---- per-row segmented scan over this warp's 64 cols ----
    float2 bhv[8];
    #pragma unroll
    for (int j = 0; j < 8; j++)
        bhv[j] = __ldg((const float2*)(bh + nw * 64 + 8 * j + 2 * lk));

    #pragma unroll
    for (int i = 0; i < 2; i++) {
        #pragma unroll
        for (int hh = 0; hh < 2; hh++) {
            const int r = 16 * i + 8 * hh + l4;
            float carry = 0.f;
            #pragma unroll
            for (int j = 0; j < 8; j++) {
                float v0 = fmaxf(acc[i][j][2 * hh]     + bhv[j].x, 0.f);
                float v1 = fmaxf(acc[i][j][2 * hh + 1] + bhv[j].y, 0.f);
                float p = v0 + v1;
                float incl = p, t;
                t = __shfl_up_sync(0xffffffffu, incl, 1, 4); if (lk >= 1) incl += t;
                t = __shfl_up_sync(0xffffffffu, incl, 2, 4); if (lk >= 2) incl += t;
                float excl = incl - p;
                acc[i][j][2 * hh]     = carry + excl + v0;
                acc[i][j][2 * hh + 1] = carry + incl;
                carry += __shfl_sync(0xffffffffu, incl, 3, 4);
            }
            if (lk == 0) seg_s[r * 8 + nw] = carry;
        }
    }
    __syncthreads();   // the ONE CTA barrier

    // ---- cross-warp segment prefix + base (fixed-order sums), store ----
    const float bbv = bb[0];
    #pragma unroll
    for (int i = 0; i < 2; i++) {
        #pragma unroll
        for (int hh = 0; hh < 2; hh++) {
            const int r = 16 * i + 8 * hh + l4;
            float g = bbv;
            #pragma unroll
            for (int s = 0; s < 8; s++)
                g += bsum_s[r * 8 + s];
            #pragma unroll
            for (int s = 0; s < 8; s++)
                if (s < nw) g += seg_s[r * 8 + s];
            float* orow = out + (size_t)(row0 + r) * TDIM + nw * 64 + 2 * lk;
            #pragma unroll
            for (int j = 0; j < 8; j++) {
                float2 o;
                o.x = acc[i][j][2 * hh]     + g;
                o.y = acc[i][j][2 * hh + 1] + g;
                *(float2*)(orow + 8 * j) = o;
            }
        }
    }
}

extern "C" void kernel_launch(void* const* d_in, const int* in_sizes, int n_in,
                              void* d_out, int out_size)
{
    const float* x  = (const float*)d_in[0];
    const float* Wh = (const float*)d_in[1];
    const float* bh = (const float*)d_in[2];
    const float* Wb = (const float*)d_in[3];
    const float* bb = (const float*)d_in[4];
    float* out = (float*)d_out;
    (void)in_sizes; (void)n_in; (void)out_size;

    prep_wh_kernel<<<256, 256>>>(Wh);
    surv_f16k_kernel<<<BROWS / MTILE, NTHREADS>>>(x, bh, Wb, bb, out);
}

// round 17
// speedup vs baseline: 2.1628x; 2.1628x over previous
#include <cuda_runtime.h>
#include <cuda_fp16.h>
#include <cstdint>

// out[b,t] = cumsum_t( relu(x @ Wh^T + bh) ) + (x @ Wb^T + bb)
//   x [16384,1024] f32, Wh [512,1024] f32, bh[512], Wb[1,1024], bb[1]
//
// fp16 mma.sync m16n8k16. CTA = 32 rows x 512 cols, 256 threads (8 warps,
// warp tile 32x64), 2 CTAs/SM, grid 512.
// R17: the CTA's whole fp16 A-tile (64KB) lives RESIDENT in smem.
//  - Prologue (16 iters, 1 barrier each): raw fp32 x streamed via 4-stage
//    cp.async ring (distance-3 slack), converted in registers into the
//    resident fragment buffer (sigma-XOR unit permutation keeps STS ~2-way
//    and reader LDS conflict-free), exact fp32 base GEMV folded in.
//  - Mainloop: ZERO barriers, ZERO cp.async: 4 LDS.128 (resident A) +
//    8 B-LDG.128 (fragment-order g_whs, consume-then-reload) + 32 MMA.
// B prepass (prep_wh) unchanged. In-register scan epilogue.

#define DDIM   1024
#define TDIM   512
#define BROWS  16384
#define MTILE  32
#define NCH    32
#define NTHREADS 256

#define FRAG_O   0                     // 65536 B resident A fragments
#define RAW_O    65536                 // 4 stages x 8704 B raw x ring
#define RAW_STG  8704                  // 32 rows x 272 B (16B pad per row)
#define DYN_BYTES (65536 + 4 * RAW_STG)   // 100352

__device__ __half g_whs[TDIM * DDIM];  // B: [chunk][jg][lane][8 halfs]

__device__ __forceinline__ void mma_f16(float* c, uint32_t a0, uint32_t a1,
                                        uint32_t a2, uint32_t a3,
                                        uint32_t b0, uint32_t b1) {
    asm volatile(
        "mma.sync.aligned.m16n8k16.row.col.f32.f16.f16.f32 "
        "{%0,%1,%2,%3}, {%4,%5,%6,%7}, {%8,%9}, {%0,%1,%2,%3};"
        : "+f"(c[0]), "+f"(c[1]), "+f"(c[2]), "+f"(c[3])
        : "r"(a0), "r"(a1), "r"(a2), "r"(a3), "r"(b0), "r"(b1));
}
__device__ __forceinline__ void cp16(void* dst_s, const void* src_g) {
    uint32_t d = (uint32_t)__cvta_generic_to_shared(dst_s);
    asm volatile("cp.async.cg.shared.global [%0], [%1], 16;" :: "r"(d), "l"(src_g));
}
__device__ __forceinline__ uint32_t f2h2(float lo, float hi) {
    __half2 h = __floats2half2_rn(lo, hi);
    return *(uint32_t*)&h;
}

// prepass: Wh -> fp16 B-fragment order (proven since R8; 256 blocks)
__global__ void __launch_bounds__(256) prep_wh_kernel(const float* __restrict__ Wh) {
    __shared__ __half sbuf[2048];
    const int b = blockIdx.x;
    const int t = threadIdx.x;
    const int c   = b >> 3;
    const int rg8 = b & 7;
    const int rl = t >> 2;
    const int q  = t & 3;
    const int T  = rg8 * 64 + rl;
    const float* wrow = Wh + (size_t)T * DDIM + c * 32 + q * 8;
    float4 v0 = *(const float4*)(wrow);
    float4 v1 = *(const float4*)(wrow + 4);
    const int jg_l = rl >> 3;
    const int l4 = T & 7;
    #pragma unroll
    for (int e = 0; e < 8; e++) {
        int k5 = q * 8 + e;
        int G = (k5 >> 4) & 1, u = (k5 >> 3) & 1, lk = (k5 & 7) >> 1, w_ = k5 & 1;
        float f = (e < 4) ? ((const float*)&v0)[e] : ((const float*)&v1)[e - 4];
        sbuf[jg_l * 256 + (4 * l4 + lk) * 8 + 4 * G + 2 * u + w_] =
            __float2half_rn(f);
    }
    __syncthreads();
    *(uint4*)((char*)g_whs + (size_t)c * 32768 + rg8 * 4096 + t * 16) =
        *(const uint4*)((const char*)sbuf + t * 16);
}

__global__ void __launch_bounds__(NTHREADS, 2)
surv_f16m_kernel(const float* __restrict__ x,
                 const float* __restrict__ bh,
                 const float* __restrict__ Wb,
                 const float* __restrict__ bb,
                 float* __restrict__ out)
{
    extern __shared__ __align__(16) char dyn[];
    __shared__ float seg_s[MTILE * 8];
    __shared__ float bsum_s[MTILE * 2];

    const int tid  = threadIdx.x;
    const int nw   = tid >> 5;
    const int lane = tid & 31;
    const int l4   = lane >> 2;
    const int lk   = lane & 3;
    const int tile = blockIdx.x;
    const int row0 = tile * MTILE;

    // ======== PROLOGUE: raw x -> resident fp16 A fragments ========
    // cp.async addressing: this thread copies segs tid and tid+256
    const char* xsrc = (const char*)x + (size_t)row0 * 4096;
    const int cpr0 = tid >> 4, cpsc = (tid & 15) * 16;
    // convert addressing: r = row (0..31), cl = chunk parity, q = 8-float grp
    const int pr_cl = tid >> 7;
    const int pr_r  = (tid & 127) >> 2;
    const int pr_q  = tid & 3;
    const int L4 = pr_r & 7;
    const int Q  = 2 * (pr_r >> 4) + (pr_q >> 1);
    const int intra = 8 * (pr_q & 1) + 4 * ((pr_r >> 3) & 1);
    int um[4];   // sigma unit per m
    #pragma unroll
    for (int m = 0; m < 4; m++)
        um[m] = ((4 * L4 + m) ^ ((L4 >> 1) & 3)) * 16;
    const char* rawrd0 = dyn + RAW_O + pr_r * 272 + pr_cl * 128 + pr_q * 32;

    float bacc = 0.f;

    // pre-issue raw stages 0..2
    #pragma unroll
    for (int s = 0; s < 3; s++) {
        char* dst = dyn + RAW_O + s * RAW_STG;
        const char* src = xsrc + s * 256;
        cp16(dst + cpr0 * 272 + cpsc,        src + (size_t)cpr0 * 4096 + cpsc);
        cp16(dst + (cpr0 + 16) * 272 + cpsc, src + (size_t)(cpr0 + 16) * 4096 + cpsc);
        asm volatile("cp.async.commit_group;" ::: "memory");
    }

    #pragma unroll 1
    for (int it = 0; it < 16; it++) {
        if (it < 14)       asm volatile("cp.async.wait_group 2;" ::: "memory");
        else if (it == 14) asm volatile("cp.async.wait_group 1;" ::: "memory");
        else               asm volatile("cp.async.wait_group 0;" ::: "memory");
        __syncthreads();

        if (it + 3 < 16) {   // refill stage (it+3)&3 (converted at it-1, safe)
            char* dst = dyn + RAW_O + ((it + 3) & 3) * RAW_STG;
            const char* src = xsrc + (it + 3) * 256;
            cp16(dst + cpr0 * 272 + cpsc,        src + (size_t)cpr0 * 4096 + cpsc);
            cp16(dst + (cpr0 + 16) * 272 + cpsc, src + (size_t)(cpr0 + 16) * 4096 + cpsc);
            asm volatile("cp.async.commit_group;" ::: "memory");
        }

        const char* rb = rawrd0 + (it & 3) * RAW_STG;
        float4 v0 = *(const float4*)(rb);
        float4 v1 = *(const float4*)(rb + 16);
        const int chunk = 2 * it + pr_cl;
        {
            float4 w0 = __ldg((const float4*)(Wb + chunk * 32 + pr_q * 8));
            float4 w1 = __ldg((const float4*)(Wb + chunk * 32 + pr_q * 8 + 4));
            bacc = fmaf(v0.x, w0.x, bacc); bacc = fmaf(v0.y, w0.y, bacc);
            bacc = fmaf(v0.z, w0.z, bacc); bacc = fmaf(v0.w, w0.w, bacc);
            bacc = fmaf(v1.x, w1.x, bacc); bacc = fmaf(v1.y, w1.y, bacc);
            bacc = fmaf(v1.z, w1.z, bacc); bacc = fmaf(v1.w, w1.w, bacc);
        }
        char* qbase = dyn + FRAG_O + chunk * 2048 + Q * 512 + intra;
        *(uint32_t*)(qbase + um[0]) = f2h2(v0.x, v0.y);
        *(uint32_t*)(qbase + um[1]) = f2h2(v0.z, v0.w);
        *(uint32_t*)(qbase + um[2]) = f2h2(v1.x, v1.y);
        *(uint32_t*)(qbase + um[3]) = f2h2(v1.z, v1.w);
    }

    // base partials: reduce the 4 q-lanes, store per (row, cl)
    bacc += __shfl_down_sync(0xffffffffu, bacc, 2, 4);
    bacc += __shfl_down_sync(0xffffffffu, bacc, 1, 4);
    if (pr_q == 0) bsum_s[pr_r * 2 + pr_cl] = bacc;
    __syncthreads();   // fragments + bsum visible; prologue done

    // ======== MAINLOOP: no barriers, no cp.async ========
    const char* bgm = (const char*)g_whs + nw * 4096 + lane * 16;
    const int u16 = ((4 * l4 + lk) ^ ((l4 >> 1) & 3)) * 16;   // sigma reader

    float acc[2][8][4];
    #pragma unroll
    for (int i = 0; i < 2; i++)
        #pragma unroll
        for (int j = 0; j < 8; j++)
            #pragma unroll
            for (int q = 0; q < 4; q++) acc[i][j][q] = 0.f;

    uint4 LB[8];
    #pragma unroll
    for (int j = 0; j < 8; j++)
        LB[j] = *(const uint4*)(bgm + j * 512);

    #pragma unroll 1
    for (int c = 0; c < NCH; c++) {
        const char* xaddr = dyn + FRAG_O + c * 2048 + u16;
        uint4 LA00 = *(const uint4*)(xaddr);            // i0 G0
        uint4 LA01 = *(const uint4*)(xaddr + 512);      // i0 G1
        uint4 LA10 = *(const uint4*)(xaddr + 1024);     // i1 G0
        uint4 LA11 = *(const uint4*)(xaddr + 1536);     // i1 G1

        const char* bnext = bgm + (size_t)((c + 1 < NCH) ? (c + 1) : c) * 32768;
        #pragma unroll
        for (int j = 0; j < 8; j++) {
            uint4 b = LB[j];
            mma_f16(acc[0][j], LA00.x, LA00.y, LA00.z, LA00.w, b.x, b.y);
            mma_f16(acc[1][j], LA10.x, LA10.y, LA10.z, LA10.w, b.x, b.y);
            mma_f16(acc[0][j], LA01.x, LA01.y, LA01.z, LA01.w, b.z, b.w);
            mma_f16(acc[1][j], LA11.x, LA11.y, LA11.z, LA11.w, b.z, b.w);
            LB[j] = *(const uint4*)(bnext + j * 512);   // ~full chunk of slack
        }
    }

    // ======== EPILOGUE ========
    float2 bhv[8];
    #pragma unroll
    for (int j = 0; j < 8; j++)
        bhv[j] = __ldg((const float2*)(bh + nw * 64 + 8 * j + 2 * lk));

    #pragma unroll
    for (int i = 0; i < 2; i++) {
        #pragma unroll
        for (int hh = 0; hh < 2; hh++) {
            const int r = 16 * i + 8 * hh + l4;
            float carry = 0.f;
            #pragma unroll
            for (int j = 0; j < 8; j++) {
                float v0 = fmaxf(acc[i][j][2 * hh]     + bhv[j].x, 0.f);
                float v1 = fmaxf(acc[i][j][2 * hh + 1] + bhv[j].y, 0.f);
                float p = v0 + v1;
                float incl = p, t;
                t = __shfl_up_sync(0xffffffffu, incl, 1, 4); if (lk >= 1) incl += t;
                t = __shfl_up_sync(0xffffffffu, incl, 2, 4); if (lk >= 2) incl += t;
                float excl = incl - p;
                acc[i][j][2 * hh]     = carry + excl + v0;
                acc[i][j][2 * hh + 1] = carry + incl;
                carry += __shfl_sync(0xffffffffu, incl, 3, 4);
            }
            if (lk == 0) seg_s[r * 8 + nw] = carry;
        }
    }
    __syncthreads();

    const float bbv = bb[0];
    #pragma unroll
    for (int i = 0; i < 2; i++) {
        #pragma unroll
        for (int hh = 0; hh < 2; hh++) {
            const int r = 16 * i + 8 * hh + l4;
            float g = bbv + bsum_s[r * 2] + bsum_s[r * 2 + 1];
            #pragma unroll
            for (int s = 0; s < 8; s++)
                if (s < nw) g += seg_s[r * 8 + s];
            float* orow = out + (size_t)(row0 + r) * TDIM + nw * 64 + 2 * lk;
            #pragma unroll
            for (int j = 0; j < 8; j++) {
                float2 o;
                o.x = acc[i][j][2 * hh]     + g;
                o.y = acc[i][j][2 * hh + 1] + g;
                *(float2*)(orow + 8 * j) = o;
            }
        }
    }
}

extern "C" void kernel_launch(void* const* d_in, const int* in_sizes, int n_in,
                              void* d_out, int out_size)
{
    const float* x  = (const float*)d_in[0];
    const float* Wh = (const float*)d_in[1];
    const float* bh = (const float*)d_in[2];
    const float* Wb = (const float*)d_in[3];
    const float* bb = (const float*)d_in[4];
    float* out = (float*)d_out;
    (void)in_sizes; (void)n_in; (void)out_size;

    static bool attr_set = false;
    if (!attr_set) {
        cudaFuncSetAttribute(surv_f16m_kernel,
                             cudaFuncAttributeMaxDynamicSharedMemorySize,
                             DYN_BYTES);
        attr_set = true;
    }

    prep_wh_kernel<<<256, 256>>>(Wh);
    surv_f16m_kernel<<<BROWS / MTILE, NTHREADS, DYN_BYTES>>>(x, bh, Wb, bb, out);
}